// round 9
// baseline (speedup 1.0000x reference)
#include <cuda_runtime.h>
#include <cuda_bf16.h>
#include <math.h>

// Problem shapes (fixed dataset): N=F=16384, G=8192, S=16
#define MAXN    16384
#define MAXF    16384
#define MAXG    8192
#define SMP     16
#define MAXQR   (MAXG * SMP)        // 131072 reverse queries

// Uniform grid over [-4.75, 4.75]^3; out-of-range points clamp into edge
// cells (conservative for the shell termination bound).
#define GD      48
#define CELLS   (GD * GD * GD)      // 110592
#define LOB     (-4.75f)
#define HCELL   (9.5f / (float)GD)
#define SCANT   1024
#define PERT    (CELLS / SCANT)     // 108

__device__ int    g_cnt[4][CELLS];
__device__ int    g_starts[4][CELLS + 1];
__device__ int    g_cursor[4][CELLS];
__device__ float4 g_sref0[MAXN];    // orig vertices  (x,y,z,|p|^2), cell-sorted
__device__ float4 g_sref1[MAXF];    // orig barycenters
__device__ float4 g_sq0[MAXQR];     // reverse queries, cell-sorted
__device__ float  g_sp0[MAXQR];
__device__ float4 g_sq1[MAXG];      // forward queries
__device__ float  g_sp1[MAXG];
__device__ double g_fwd, g_rev;
__device__ unsigned g_maxbits;

__device__ __forceinline__ int cellof(float x) {
    int c = (int)floorf((x - LOB) * (1.0f / HCELL));
    return min(max(c, 0), GD - 1);
}

// Deterministic item generator shared by count & fill passes.
__device__ __forceinline__ void item(
    int idx,
    const float* __restrict__ ov, const int* __restrict__ of,
    const float* __restrict__ sv, const int* __restrict__ sf,
    const float* __restrict__ probs,
    const float* __restrict__ r1, const float* __restrict__ r2,
    int N, int F, int G, int S,
    int& set, float& x, float& y, float& z, float& prob)
{
    if (idx < N) {
        set = 0; prob = 0.f;
        x = ov[3*idx]; y = ov[3*idx+1]; z = ov[3*idx+2];
    } else if (idx < N + F) {
        set = 1; prob = 0.f;
        int f = idx - N;
        int i0 = of[3*f], i1 = of[3*f+1], i2 = of[3*f+2];
        x = (ov[3*i0  ] + ov[3*i1  ] + ov[3*i2  ]) * (1.f/3.f);
        y = (ov[3*i0+1] + ov[3*i1+1] + ov[3*i2+1]) * (1.f/3.f);
        z = (ov[3*i0+2] + ov[3*i1+2] + ov[3*i2+2]) * (1.f/3.f);
    } else if (idx < N + F + G * S) {
        set = 2;
        int q = idx - N - F;
        int g = q / S;
        int i0 = sf[3*g], i1 = sf[3*g+1], i2 = sf[3*g+2];
        float sq = sqrtf(r1[q]);
        float rr2 = r2[q];
        float u = 1.f - sq, v = sq * (1.f - rr2), w = sq * rr2;
        x = u*sv[3*i0  ] + v*sv[3*i1  ] + w*sv[3*i2  ];
        y = u*sv[3*i0+1] + v*sv[3*i1+1] + w*sv[3*i2+1];
        z = u*sv[3*i0+2] + v*sv[3*i1+2] + w*sv[3*i2+2];
        prob = probs[g];
    } else {
        set = 3;
        int g = idx - N - F - G * S;
        int i0 = sf[3*g], i1 = sf[3*g+1], i2 = sf[3*g+2];
        x = (sv[3*i0  ] + sv[3*i1  ] + sv[3*i2  ]) * (1.f/3.f);
        y = (sv[3*i0+1] + sv[3*i1+1] + sv[3*i2+1]) * (1.f/3.f);
        z = (sv[3*i0+2] + sv[3*i1+2] + sv[3*i2+2]) * (1.f/3.f);
        prob = probs[g];
    }
}

// ---------------------------------------------------------------------------
__global__ void k_zero()
{
    int idx = blockIdx.x * blockDim.x + threadIdx.x;
    if (idx == 0) { g_fwd = 0.0; g_rev = 0.0; g_maxbits = 0u; }
    if (idx < 4 * CELLS) ((int*)g_cnt)[idx] = 0;
}

__global__ void k_count(const float* __restrict__ ov, const int* __restrict__ of,
                        const float* __restrict__ sv, const int* __restrict__ sf,
                        const float* __restrict__ probs,
                        const float* __restrict__ r1, const float* __restrict__ r2,
                        int N, int F, int G, int S, int T)
{
    int idx = blockIdx.x * blockDim.x + threadIdx.x;
    if (idx >= T) return;
    int set; float x, y, z, p;
    item(idx, ov, of, sv, sf, probs, r1, r2, N, F, G, S, set, x, y, z, p);
    int cid = (cellof(z) * GD + cellof(y)) * GD + cellof(x);
    atomicAdd(&g_cnt[set][cid], 1);
}

__global__ void k_scan()
{
    const int a = blockIdx.x;
    const int t = threadIdx.x;
    __shared__ int part[SCANT];
    const int base = t * PERT;
    int sum = 0;
    #pragma unroll 4
    for (int i = 0; i < PERT; i++) sum += g_cnt[a][base + i];
    part[t] = sum;
    __syncthreads();
    for (int off = 1; off < SCANT; off <<= 1) {
        int v = (t >= off) ? part[t - off] : 0;
        __syncthreads();
        part[t] += v;
        __syncthreads();
    }
    int run = part[t] - sum;
    for (int i = 0; i < PERT; i++) {
        int c = g_cnt[a][base + i];
        g_starts[a][base + i] = run;
        g_cursor[a][base + i] = run;
        run += c;
    }
    if (t == SCANT - 1) g_starts[a][CELLS] = run;
}

__global__ void k_fill(const float* __restrict__ ov, const int* __restrict__ of,
                       const float* __restrict__ sv, const int* __restrict__ sf,
                       const float* __restrict__ probs,
                       const float* __restrict__ r1, const float* __restrict__ r2,
                       int N, int F, int G, int S, int T)
{
    int idx = blockIdx.x * blockDim.x + threadIdx.x;
    if (idx >= T) return;
    int set; float x, y, z, p;
    item(idx, ov, of, sv, sf, probs, r1, r2, N, F, G, S, set, x, y, z, p);
    int cid = (cellof(z) * GD + cellof(y)) * GD + cellof(x);
    int pos = atomicAdd(&g_cursor[set][cid], 1);
    float ww = x*x + y*y + z*z;
    float4 v4 = make_float4(x, y, z, ww);
    if      (set == 0) g_sref0[pos] = v4;
    else if (set == 1) g_sref1[pos] = v4;
    else if (set == 2) { g_sq0[pos] = v4; g_sp0[pos] = p; }
    else               { g_sq1[pos] = v4; g_sp1[pos] = p; }
}

// ---------------------------------------------------------------------------
// Warp-per-query grid NN. Blocks [0, brev): reverse; [brev, ...): forward.
// The 32 lanes of a warp share one query: shell rows are enumerated
// arithmetically and distributed across lanes (32 concurrent row scans),
// then a shfl min-reduction feeds the exact termination test.
// ---------------------------------------------------------------------------
#define QT   256
#define WPB  (QT / 32)
__global__ void __launch_bounds__(QT)
k_query(int brev, int nq_rev, int nq_fwd)
{
    const bool rev = (blockIdx.x < (unsigned)brev);
    const float4* __restrict__ refs = rev ? g_sref0     : g_sref1;
    const int*    __restrict__ st   = rev ? g_starts[0] : g_starts[1];
    const float4* __restrict__ qarr = rev ? g_sq0       : g_sq1;
    const float*  __restrict__ parr = rev ? g_sp0       : g_sp1;
    const int nq = rev ? nq_rev : nq_fwd;

    const int warp = threadIdx.x >> 5;
    const int lane = threadIdx.x & 31;
    const int wq = (rev ? blockIdx.x : blockIdx.x - brev) * WPB + warp;

    float contrib = 0.f, d = 0.f;

    if (wq < nq) {
        const float4 Q = qarr[wq];
        const float a = -2.f * Q.x, b = -2.f * Q.y, c = -2.f * Q.z;
        const float qq = Q.w;
        const int cx = cellof(Q.x), cy = cellof(Q.y), cz = cellof(Q.z);

        float best = 3.4e38f;    // min(|p|^2 - 2 q.p);  d^2 = best + qq

        for (int r = 0; r < GD; r++) {
            const int xlo = max(cx - r, 0), xhi = min(cx + r, GD - 1);
            const int ylo = max(cy - r, 0), yhi = min(cy + r, GD - 1);
            const int zlo = max(cz - r, 0), zhi = min(cz + r, GD - 1);
            const unsigned ny   = (unsigned)(yhi - ylo + 1);
            const int      xlen = xhi - xlo + 1;

            // z caps (full faces)
            int capcnt = 0, capz0 = 0, capz1 = 0;
            if (cz - r >= 0)               { capz0 = cz - r; capcnt = 1; }
            if (r > 0 && cz + r <= GD - 1) { if (capcnt == 0) capz0 = cz + r; else capz1 = cz + r; capcnt++; }
            // interior z band
            const int izlo = max(cz - r + 1, 0), izhi = min(cz + r - 1, GD - 1);
            const unsigned nzint = (unsigned)max(izhi - izlo + 1, 0);
            // y sides (full-x rows, interior z)
            int nys = 0, ys0 = 0, ys1 = 0;
            if (cy - r >= 0)               { ys0 = cy - r; nys = 1; }
            if (r > 0 && cy + r <= GD - 1) { if (nys == 0) ys0 = cy + r; else ys1 = cy + r; nys++; }
            // interior y band
            const int iylo = max(cy - r + 1, 0), iyhi = min(cy + r - 1, GD - 1);
            const unsigned nyint = (unsigned)max(iyhi - iylo + 1, 0);
            // x edges (single cells, interior z & y)
            int nxs = 0, xs0 = 0, xs1 = 0;
            if (cx - r >= 0)               { xs0 = cx - r; nxs = 1; }
            if (r > 0 && cx + r <= GD - 1) { if (nxs == 0) xs0 = cx + r; else xs1 = cx + r; nxs++; }

            const unsigned nA = (unsigned)capcnt * ny;
            const unsigned nB = (unsigned)nys * nzint;
            const unsigned nzy = nzint * nyint;
            const unsigned nC = (unsigned)nxs * nzy;
            const unsigned tot = nA + nB + nC;

            for (unsigned t = (unsigned)lane; t < tot; t += 32) {
                int c0, len;
                if (t < nA) {
                    unsigned ci = t / ny, yr = t - ci * ny;
                    int z = ci ? capz1 : capz0;
                    c0 = (z * GD + (ylo + (int)yr)) * GD + xlo; len = xlen;
                } else if (t < nA + nB) {
                    unsigned t2 = t - nA;
                    unsigned si = t2 / nzint, zi = t2 - si * nzint;
                    int y = si ? ys1 : ys0;
                    c0 = (((int)zi + izlo) * GD + y) * GD + xlo; len = xlen;
                } else {
                    unsigned t3 = t - nA - nB;
                    unsigned xi = t3 / nzy, rem = t3 - xi * nzy;
                    unsigned zi = rem / nyint, yi = rem - zi * nyint;
                    int x = xi ? xs1 : xs0;
                    c0 = (((int)zi + izlo) * GD + ((int)yi + iylo)) * GD + x; len = 1;
                }
                const int s = st[c0], e = st[c0 + len];
                for (int i = s; i < e; i++) {
                    float4 w = refs[i];
                    best = fminf(best, fmaf(a, w.x, fmaf(b, w.y, fmaf(c, w.z, w.w))));
                }
            }

            // warp-wide min, then exact termination test (uniform decision)
            #pragma unroll
            for (int o = 16; o > 0; o >>= 1)
                best = fminf(best, __shfl_xor_sync(0xFFFFFFFFu, best, o));

            const float d2 = fmaxf(best + qq, 0.f);
            const float cov = (float)r * HCELL;
            if (d2 <= cov * cov) break;
            if (xlo == 0 && ylo == 0 && zlo == 0 &&
                xhi == GD - 1 && yhi == GD - 1 && zhi == GD - 1) break;
        }

        d = sqrtf(fmaxf(best + qq, 1e-12f));
        if (lane == 0) {
            const float p = parr[wq];
            contrib = rev ? p * d : fmaf(p, d, 1e-4f * (1.f - p));
        }
    }

    // block reduce (one value per warp), one atomic per block
    __shared__ float rs[WPB], rm[WPB];
    if (lane == 0) { rs[warp] = contrib; rm[warp] = (wq < nq) ? d : 0.f; }
    __syncthreads();
    if (threadIdx.x == 0) {
        float s = 0.f, m = 0.f;
        #pragma unroll
        for (int i = 0; i < WPB; i++) { s += rs[i]; m = fmaxf(m, rm[i]); }
        atomicAdd(rev ? &g_rev : &g_fwd, (double)s);
        if (rev) atomicMax(&g_maxbits, __float_as_uint(m));
    }
}

// ---------------------------------------------------------------------------
__global__ void k_finalize(float* __restrict__ out)
{
    float maxd = __uint_as_float(g_maxbits) + 1e-8f;
    double result = g_fwd + g_rev * (0.1 / (double)maxd);
    out[0] = (float)result;
}

// ---------------------------------------------------------------------------
extern "C" void kernel_launch(void* const* d_in, const int* in_sizes, int n_in,
                              void* d_out, int out_size)
{
    const float* ov    = (const float*)d_in[0];
    const int*   of    = (const int*)  d_in[1];
    const float* sv    = (const float*)d_in[2];
    const int*   sf    = (const int*)  d_in[3];
    const float* probs = (const float*)d_in[4];
    const float* r1    = (const float*)d_in[5];
    const float* r2    = (const float*)d_in[6];

    const int N = in_sizes[0] / 3;     // 16384
    const int F = in_sizes[1] / 3;     // 16384
    const int G = in_sizes[3] / 3;     // 8192
    const int S = in_sizes[5] / G;     // 16

    const int nq_rev = G * S;          // 131072
    const int nq_fwd = G;              // 8192
    const int T = N + F + nq_rev + nq_fwd;

    k_zero <<<(4 * CELLS + 255) / 256, 256>>>();
    k_count<<<(T + 255) / 256, 256>>>(ov, of, sv, sf, probs, r1, r2, N, F, G, S, T);
    k_scan <<<4, SCANT>>>();
    k_fill <<<(T + 255) / 256, 256>>>(ov, of, sv, sf, probs, r1, r2, N, F, G, S, T);

    const int brev = (nq_rev + WPB - 1) / WPB;   // 16384 blocks of 8 warps
    const int bfwd = (nq_fwd + WPB - 1) / WPB;   // 1024
    k_query<<<brev + bfwd, QT>>>(brev, nq_rev, nq_fwd);

    k_finalize<<<1, 1>>>((float*)d_out);
}

// round 11
// speedup vs baseline: 4.7215x; 4.7215x over previous
#include <cuda_runtime.h>
#include <cuda_bf16.h>
#include <math.h>

// Problem shapes (fixed dataset): N=F=16384, G=8192, S=16
#define MAXN    16384
#define MAXF    16384
#define MAXG    8192
#define SMP     16
#define MAXQR   (MAXG * SMP)        // 131072 reverse queries
#define MAXP    (MAXQR + MAXG)

// Uniform grid over [-4.75, 4.75]^3; out-of-range points clamp into edge
// cells (conservative for the shell termination bound).
#define GD      48
#define CELLS   (GD * GD * GD)      // 110592
#define LOB     (-4.75f)
#define HCELL   (9.5f / (float)GD)
#define CHUNK   1024
#define NCH     (CELLS / CHUNK)     // 108

__device__ int    g_cnt[4][CELLS];
__device__ int    g_starts[4][CELLS + 1];
__device__ int    g_cursor[4][CELLS];
__device__ int    g_chtot[4][NCH];
__device__ int    g_choff[4][NCH];
__device__ float4 g_sref0[MAXN];    // orig vertices  (x,y,z,|p|^2), cell-sorted
__device__ float4 g_sref1[MAXF];    // orig barycenters
__device__ float4 g_sq0[MAXQR];     // reverse queries, cell-sorted
__device__ float  g_sp0[MAXQR];
__device__ float4 g_sq1[MAXG];      // forward queries
__device__ float  g_sp1[MAXG];
__device__ int    g_pidx[MAXP];     // pending (uncertified) queries
__device__ float  g_pbest[MAXP];
__device__ int    g_npend;
__device__ double g_fwd, g_rev;
__device__ unsigned g_maxbits;

__device__ __forceinline__ int cellof(float x) {
    int c = (int)floorf((x - LOB) * (1.0f / HCELL));
    return min(max(c, 0), GD - 1);
}

// Deterministic item generator shared by count & fill passes.
__device__ __forceinline__ void item(
    int idx,
    const float* __restrict__ ov, const int* __restrict__ of,
    const float* __restrict__ sv, const int* __restrict__ sf,
    const float* __restrict__ probs,
    const float* __restrict__ r1, const float* __restrict__ r2,
    int N, int F, int G, int S,
    int& set, float& x, float& y, float& z, float& prob)
{
    if (idx < N) {
        set = 0; prob = 0.f;
        x = ov[3*idx]; y = ov[3*idx+1]; z = ov[3*idx+2];
    } else if (idx < N + F) {
        set = 1; prob = 0.f;
        int f = idx - N;
        int i0 = of[3*f], i1 = of[3*f+1], i2 = of[3*f+2];
        x = (ov[3*i0  ] + ov[3*i1  ] + ov[3*i2  ]) * (1.f/3.f);
        y = (ov[3*i0+1] + ov[3*i1+1] + ov[3*i2+1]) * (1.f/3.f);
        z = (ov[3*i0+2] + ov[3*i1+2] + ov[3*i2+2]) * (1.f/3.f);
    } else if (idx < N + F + G * S) {
        set = 2;
        int q = idx - N - F;
        int g = q / S;
        int i0 = sf[3*g], i1 = sf[3*g+1], i2 = sf[3*g+2];
        float sq = sqrtf(r1[q]);
        float rr2 = r2[q];
        float u = 1.f - sq, v = sq * (1.f - rr2), w = sq * rr2;
        x = u*sv[3*i0  ] + v*sv[3*i1  ] + w*sv[3*i2  ];
        y = u*sv[3*i0+1] + v*sv[3*i1+1] + w*sv[3*i2+1];
        z = u*sv[3*i0+2] + v*sv[3*i1+2] + w*sv[3*i2+2];
        prob = probs[g];
    } else {
        set = 3;
        int g = idx - N - F - G * S;
        int i0 = sf[3*g], i1 = sf[3*g+1], i2 = sf[3*g+2];
        x = (sv[3*i0  ] + sv[3*i1  ] + sv[3*i2  ]) * (1.f/3.f);
        y = (sv[3*i0+1] + sv[3*i1+1] + sv[3*i2+1]) * (1.f/3.f);
        z = (sv[3*i0+2] + sv[3*i1+2] + sv[3*i2+2]) * (1.f/3.f);
        prob = probs[g];
    }
}

// ---------------------------------------------------------------------------
__global__ void k_zero()
{
    int idx = blockIdx.x * blockDim.x + threadIdx.x;
    if (idx == 0) { g_fwd = 0.0; g_rev = 0.0; g_maxbits = 0u; g_npend = 0; }
    if (idx < 4 * CELLS) ((int*)g_cnt)[idx] = 0;
}

__global__ void k_count(const float* __restrict__ ov, const int* __restrict__ of,
                        const float* __restrict__ sv, const int* __restrict__ sf,
                        const float* __restrict__ probs,
                        const float* __restrict__ r1, const float* __restrict__ r2,
                        int N, int F, int G, int S, int T)
{
    int idx = blockIdx.x * blockDim.x + threadIdx.x;
    if (idx >= T) return;
    int set; float x, y, z, p;
    item(idx, ov, of, sv, sf, probs, r1, r2, N, F, G, S, set, x, y, z, p);
    int cid = (cellof(z) * GD + cellof(y)) * GD + cellof(x);
    atomicAdd(&g_cnt[set][cid], 1);
}

// Chunked scan: A = per-chunk exclusive scan (coalesced), B = scan chunk
// totals, C = add offsets, write starts+cursor.
__global__ void k_scanA()
{
    const int a = blockIdx.x / NCH, j = blockIdx.x % NCH;
    const int t = threadIdx.x;
    __shared__ int sm[CHUNK];
    int v = g_cnt[a][j * CHUNK + t];
    sm[t] = v;
    __syncthreads();
    for (int off = 1; off < CHUNK; off <<= 1) {
        int u = (t >= off) ? sm[t - off] : 0;
        __syncthreads();
        sm[t] += u;
        __syncthreads();
    }
    g_starts[a][j * CHUNK + t] = sm[t] - v;     // exclusive, no chunk offset yet
    if (t == CHUNK - 1) g_chtot[a][j] = sm[t];
}

__global__ void k_scanB()
{
    const int a = blockIdx.x;
    const int t = threadIdx.x;               // 128 threads, NCH=108
    __shared__ int sm[128];
    int v = (t < NCH) ? g_chtot[a][t] : 0;
    sm[t] = v;
    __syncthreads();
    for (int off = 1; off < 128; off <<= 1) {
        int u = (t >= off) ? sm[t - off] : 0;
        __syncthreads();
        sm[t] += u;
        __syncthreads();
    }
    if (t < NCH) g_choff[a][t] = sm[t] - v;
    if (t == NCH - 1) g_starts[a][CELLS] = sm[t];
}

__global__ void k_scanC()
{
    const int a = blockIdx.x / NCH, j = blockIdx.x % NCH;
    const int t = threadIdx.x;
    const int idx = j * CHUNK + t;
    int s = g_starts[a][idx] + g_choff[a][j];
    g_starts[a][idx] = s;
    g_cursor[a][idx] = s;
}

__global__ void k_fill(const float* __restrict__ ov, const int* __restrict__ of,
                       const float* __restrict__ sv, const int* __restrict__ sf,
                       const float* __restrict__ probs,
                       const float* __restrict__ r1, const float* __restrict__ r2,
                       int N, int F, int G, int S, int T)
{
    int idx = blockIdx.x * blockDim.x + threadIdx.x;
    if (idx >= T) return;
    int set; float x, y, z, p;
    item(idx, ov, of, sv, sf, probs, r1, r2, N, F, G, S, set, x, y, z, p);
    int cid = (cellof(z) * GD + cellof(y)) * GD + cellof(x);
    int pos = atomicAdd(&g_cursor[set][cid], 1);
    float ww = x*x + y*y + z*z;
    float4 v4 = make_float4(x, y, z, ww);
    if      (set == 0) g_sref0[pos] = v4;
    else if (set == 1) g_sref1[pos] = v4;
    else if (set == 2) { g_sq0[pos] = v4; g_sp0[pos] = p; }
    else               { g_sq1[pos] = v4; g_sp1[pos] = p; }
}

// ---------------------------------------------------------------------------
// Phase 1: thread-per-query flat 3x3x3 scan. All 9 row ranges loaded up
// front (batched, MLP~18), tight candidate loop, certify with d <= h
// (sound: after the full 3^3 box, any unscanned cell is Chebyshev >= 2
// away, so any unscanned point is >= 1*h from the query).
// Uncertified queries go to the pending list with their seeded best.
// ---------------------------------------------------------------------------
#define QT 256
__global__ void __launch_bounds__(QT)
k_query1(int brev, int nq_rev, int nq_fwd)
{
    const bool rev = (blockIdx.x < (unsigned)brev);
    const float4* __restrict__ refs = rev ? g_sref0     : g_sref1;
    const int*    __restrict__ st   = rev ? g_starts[0] : g_starts[1];
    const float4* __restrict__ qarr = rev ? g_sq0       : g_sq1;
    const float*  __restrict__ parr = rev ? g_sp0       : g_sp1;
    const int nq = rev ? nq_rev : nq_fwd;
    const int qi = (rev ? blockIdx.x : blockIdx.x - brev) * QT + threadIdx.x;

    float contrib = 0.f, dmax = 0.f;

    if (qi < nq) {
        const float4 Q = qarr[qi];
        const float a = -2.f * Q.x, b = -2.f * Q.y, c = -2.f * Q.z;
        const float qq = Q.w;
        const int cx = cellof(Q.x), cy = cellof(Q.y), cz = cellof(Q.z);
        const int xlo = max(cx - 1, 0), xhi = min(cx + 1, GD - 1);
        const int xn  = xhi - xlo + 1;

        // all 9 row ranges up front (independent loads)
        int s[9], e[9];
        #pragma unroll
        for (int dz = 0; dz < 3; dz++) {
            #pragma unroll
            for (int dy = 0; dy < 3; dy++) {
                const int z = cz + dz - 1, y = cy + dy - 1;
                const int k = dz * 3 + dy;
                if (z < 0 || z >= GD || y < 0 || y >= GD) { s[k] = 0; e[k] = 0; }
                else {
                    const int c0 = (z * GD + y) * GD + xlo;
                    s[k] = st[c0]; e[k] = st[c0 + xn];
                }
            }
        }

        float best = 3.4e38f;    // min(|p|^2 - 2 q.p);  d^2 = best + qq
        #pragma unroll
        for (int k = 0; k < 9; k++) {
            for (int i = s[k]; i < e[k]; i++) {
                float4 w = refs[i];
                best = fminf(best, fmaf(a, w.x, fmaf(b, w.y, fmaf(c, w.z, w.w))));
            }
        }

        const float d2 = fmaxf(best + qq, 0.f);
        if (d2 <= HCELL * HCELL) {
            // certified exact NN
            const float d = sqrtf(fmaxf(d2, 1e-12f));
            const float p = parr[qi];
            contrib = rev ? p * d : fmaf(p, d, 1e-4f * (1.f - p));
            if (rev) dmax = d;
        } else {
            int pos = atomicAdd(&g_npend, 1);   // warp-aggregated by ptxas
            g_pidx[pos]  = rev ? qi : (qi | 0x40000000);
            g_pbest[pos] = best;
        }
    }

    // block reduce (block is uniformly rev or fwd)
    float sv = contrib, mv = dmax;
    #pragma unroll
    for (int o = 16; o > 0; o >>= 1) {
        sv += __shfl_xor_sync(0xFFFFFFFFu, sv, o);
        mv = fmaxf(mv, __shfl_xor_sync(0xFFFFFFFFu, mv, o));
    }
    __shared__ float rs[QT / 32], rm[QT / 32];
    const int warp = threadIdx.x >> 5, lane = threadIdx.x & 31;
    if (lane == 0) { rs[warp] = sv; rm[warp] = mv; }
    __syncthreads();
    if (threadIdx.x == 0) {
        float s2 = 0.f, m2 = 0.f;
        #pragma unroll
        for (int i = 0; i < QT / 32; i++) { s2 += rs[i]; m2 = fmaxf(m2, rm[i]); }
        atomicAdd(rev ? &g_rev : &g_fwd, (double)s2);
        if (rev) atomicMax(&g_maxbits, __float_as_uint(m2));
    }
}

// ---------------------------------------------------------------------------
// Phase 2: warp-per-pending-query, grid-stride. Generic shell walk from r=2
// with seeded best; rows distributed across the 32 lanes.
// ---------------------------------------------------------------------------
#define QT2   256
#define NB2   592
__global__ void __launch_bounds__(QT2)
k_query2()
{
    const int lane = threadIdx.x & 31;
    const int wid  = threadIdx.x >> 5;
    const int gw   = blockIdx.x * (QT2 / 32) + wid;
    const int nw   = NB2 * (QT2 / 32);
    const int npend = g_npend;

    float rsum = 0.f, fsum = 0.f, rmax = 0.f;

    for (int w = gw; w < npend; w += nw) {
        const int code = g_pidx[w];
        const bool rev = !(code & 0x40000000);
        const int qi = code & 0x3FFFFFFF;
        const float4* __restrict__ refs = rev ? g_sref0     : g_sref1;
        const int*    __restrict__ st   = rev ? g_starts[0] : g_starts[1];
        const float4 Q = rev ? g_sq0[qi] : g_sq1[qi];
        const float a = -2.f * Q.x, b = -2.f * Q.y, c = -2.f * Q.z;
        const float qq = Q.w;
        const int cx = cellof(Q.x), cy = cellof(Q.y), cz = cellof(Q.z);

        float best = g_pbest[w];

        for (int r = 2; r < GD; r++) {
            const int xlo = max(cx - r, 0), xhi = min(cx + r, GD - 1);
            const int ylo = max(cy - r, 0), yhi = min(cy + r, GD - 1);
            const int zlo = max(cz - r, 0), zhi = min(cz + r, GD - 1);
            const unsigned ny   = (unsigned)(yhi - ylo + 1);
            const int      xlen = xhi - xlo + 1;

            int capcnt = 0, capz0 = 0, capz1 = 0;
            if (cz - r >= 0)      { capz0 = cz - r; capcnt = 1; }
            if (cz + r <= GD - 1) { if (capcnt == 0) capz0 = cz + r; else capz1 = cz + r; capcnt++; }
            const int izlo = max(cz - r + 1, 0), izhi = min(cz + r - 1, GD - 1);
            const unsigned nzint = (unsigned)max(izhi - izlo + 1, 0);
            int nys = 0, ys0 = 0, ys1 = 0;
            if (cy - r >= 0)      { ys0 = cy - r; nys = 1; }
            if (cy + r <= GD - 1) { if (nys == 0) ys0 = cy + r; else ys1 = cy + r; nys++; }
            const int iylo = max(cy - r + 1, 0), iyhi = min(cy + r - 1, GD - 1);
            const unsigned nyint = (unsigned)max(iyhi - iylo + 1, 0);
            int nxs = 0, xs0 = 0, xs1 = 0;
            if (cx - r >= 0)      { xs0 = cx - r; nxs = 1; }
            if (cx + r <= GD - 1) { if (nxs == 0) xs0 = cx + r; else xs1 = cx + r; nxs++; }

            const unsigned nA = (unsigned)capcnt * ny;
            const unsigned nB = (unsigned)nys * nzint;
            const unsigned nzy = nzint * nyint;
            const unsigned nC = (unsigned)nxs * nzy;
            const unsigned tot = nA + nB + nC;

            for (unsigned t = (unsigned)lane; t < tot; t += 32) {
                int c0, len;
                if (t < nA) {
                    unsigned ci = t / ny, yr = t - ci * ny;
                    int z = ci ? capz1 : capz0;
                    c0 = (z * GD + (ylo + (int)yr)) * GD + xlo; len = xlen;
                } else if (t < nA + nB) {
                    unsigned t2 = t - nA;
                    unsigned si = t2 / nzint, zi = t2 - si * nzint;
                    int y = si ? ys1 : ys0;
                    c0 = (((int)zi + izlo) * GD + y) * GD + xlo; len = xlen;
                } else {
                    unsigned t3 = t - nA - nB;
                    unsigned xi = t3 / nzy, rem = t3 - xi * nzy;
                    unsigned zi = rem / nyint, yi = rem - zi * nyint;
                    int x = xi ? xs1 : xs0;
                    c0 = (((int)zi + izlo) * GD + ((int)yi + iylo)) * GD + x; len = 1;
                }
                const int s = st[c0], e = st[c0 + len];
                for (int i = s; i < e; i++) {
                    float4 wv = refs[i];
                    best = fminf(best, fmaf(a, wv.x, fmaf(b, wv.y, fmaf(c, wv.z, wv.w))));
                }
            }

            #pragma unroll
            for (int o = 16; o > 0; o >>= 1)
                best = fminf(best, __shfl_xor_sync(0xFFFFFFFFu, best, o));

            const float d2 = fmaxf(best + qq, 0.f);
            const float cov = (float)r * HCELL;
            if (d2 <= cov * cov) break;
            if (xlo == 0 && ylo == 0 && zlo == 0 &&
                xhi == GD - 1 && yhi == GD - 1 && zhi == GD - 1) break;
        }

        if (lane == 0) {
            const float d = sqrtf(fmaxf(best + qq, 1e-12f));
            const float p = rev ? g_sp0[qi] : g_sp1[qi];
            if (rev) { rsum += p * d; rmax = fmaxf(rmax, d); }
            else     { fsum += fmaf(p, d, 1e-4f * (1.f - p)); }
        }
    }

    __shared__ float shr[QT2 / 32], shf[QT2 / 32], shm[QT2 / 32];
    if (lane == 0) { shr[wid] = rsum; shf[wid] = fsum; shm[wid] = rmax; }
    __syncthreads();
    if (threadIdx.x == 0) {
        float r2s = 0.f, f2s = 0.f, m2 = 0.f;
        #pragma unroll
        for (int i = 0; i < QT2 / 32; i++) {
            r2s += shr[i]; f2s += shf[i]; m2 = fmaxf(m2, shm[i]);
        }
        if (r2s != 0.f) atomicAdd(&g_rev, (double)r2s);
        if (f2s != 0.f) atomicAdd(&g_fwd, (double)f2s);
        atomicMax(&g_maxbits, __float_as_uint(m2));
    }
}

// ---------------------------------------------------------------------------
__global__ void k_finalize(float* __restrict__ out)
{
    float maxd = __uint_as_float(g_maxbits) + 1e-8f;
    double result = g_fwd + g_rev * (0.1 / (double)maxd);
    out[0] = (float)result;
}

// ---------------------------------------------------------------------------
extern "C" void kernel_launch(void* const* d_in, const int* in_sizes, int n_in,
                              void* d_out, int out_size)
{
    const float* ov    = (const float*)d_in[0];
    const int*   of    = (const int*)  d_in[1];
    const float* sv    = (const float*)d_in[2];
    const int*   sf    = (const int*)  d_in[3];
    const float* probs = (const float*)d_in[4];
    const float* r1    = (const float*)d_in[5];
    const float* r2    = (const float*)d_in[6];

    const int N = in_sizes[0] / 3;     // 16384
    const int F = in_sizes[1] / 3;     // 16384
    const int G = in_sizes[3] / 3;     // 8192
    const int S = in_sizes[5] / G;     // 16

    const int nq_rev = G * S;          // 131072
    const int nq_fwd = G;              // 8192
    const int T = N + F + nq_rev + nq_fwd;

    k_zero <<<(4 * CELLS + 255) / 256, 256>>>();
    k_count<<<(T + 255) / 256, 256>>>(ov, of, sv, sf, probs, r1, r2, N, F, G, S, T);
    k_scanA<<<4 * NCH, CHUNK>>>();
    k_scanB<<<4, 128>>>();
    k_scanC<<<4 * NCH, CHUNK>>>();
    k_fill <<<(T + 255) / 256, 256>>>(ov, of, sv, sf, probs, r1, r2, N, F, G, S, T);

    const int brev = (nq_rev + QT - 1) / QT;   // 512
    const int bfwd = (nq_fwd + QT - 1) / QT;   // 32
    k_query1<<<brev + bfwd, QT>>>(brev, nq_rev, nq_fwd);
    k_query2<<<NB2, QT2>>>();

    k_finalize<<<1, 1>>>((float*)d_out);
}